// round 1
// baseline (speedup 1.0000x reference)
#include <cuda_runtime.h>
#include <stdint.h>

#define BATCH 64
#define NPTS  131072
#define MPTS  2048
#define CHUNK 4096
#define NBLK  (NPTS / CHUNK)   // 32 chunks per batch

// ---- scratch (device globals; no runtime allocation) ----
__device__ int      g_masked_idx[BATCH * NPTS];          // stable-compacted masked indices
__device__ unsigned g_maskbits[BATCH * NPTS / 32];       // 1 bit per point
__device__ int      g_blockcnt[BATCH * NBLK];
__device__ float    g_blocksum[BATCH * NBLK * 3];
__device__ int      g_blockoff[BATCH * NBLK];
__device__ int      g_cnt[BATCH];
__device__ float    g_mean[BATCH * 3];

// ---------------- Threefry-2x32 (matches JAX exactly) ----------------
__host__ __device__ inline void threefry2x32(uint32_t k0, uint32_t k1,
                                             uint32_t c0, uint32_t c1,
                                             uint32_t& o0, uint32_t& o1) {
    uint32_t ks2 = k0 ^ k1 ^ 0x1BD11BDAu;
    uint32_t x0 = c0 + k0, x1 = c1 + k1;
#define TF_ROUND(r) { x0 += x1; x1 = (x1 << (r)) | (x1 >> (32 - (r))); x1 ^= x0; }
    TF_ROUND(13) TF_ROUND(15) TF_ROUND(26) TF_ROUND(6)
    x0 += k1;  x1 += ks2 + 1u;
    TF_ROUND(17) TF_ROUND(29) TF_ROUND(16) TF_ROUND(24)
    x0 += ks2; x1 += k0 + 2u;
    TF_ROUND(13) TF_ROUND(15) TF_ROUND(26) TF_ROUND(6)
    x0 += k0;  x1 += k1 + 3u;
    TF_ROUND(17) TF_ROUND(29) TF_ROUND(16) TF_ROUND(24)
    x0 += k1;  x1 += ks2 + 4u;
    TF_ROUND(13) TF_ROUND(15) TF_ROUND(26) TF_ROUND(6)
    x0 += ks2; x1 += k0 + 5u;
#undef TF_ROUND
    o0 = x0; o1 = x1;
}

// ---------------- Kernel 1: mask bits + per-chunk count & masked-xyz sums ----------------
__global__ void k_mask_stats(const float* __restrict__ pc,
                             const float* __restrict__ logits) {
    const int chunk = blockIdx.x;           // 0..NBLK-1
    const int b     = blockIdx.y;           // 0..BATCH-1
    const int t     = threadIdx.x;          // 256 threads
    const int lane  = t & 31, warp = t >> 5;

    const float*  l0 = logits + (size_t)b * 2 * NPTS;
    const float*  l1 = l0 + NPTS;
    const float4* p4 = (const float4*)pc + (size_t)b * NPTS;
    const int base = chunk * CHUNK;

    int   cnt = 0;
    float sx = 0.f, sy = 0.f, sz = 0.f;

    #pragma unroll
    for (int it = 0; it < CHUNK / 256; ++it) {
        const int n = base + it * 256 + t;
        const bool m = __ldg(&l0[n]) < __ldg(&l1[n]);
        const unsigned bal = __ballot_sync(0xffffffffu, m);
        if (lane == 0)
            g_maskbits[((size_t)b * NPTS + (size_t)(base + it * 256 + warp * 32)) >> 5] = bal;
        const float4 p = __ldg(&p4[n]);
        if (m) { sx += p.x; sy += p.y; sz += p.z; ++cnt; }
    }

    // warp reduce
    #pragma unroll
    for (int o = 16; o; o >>= 1) {
        cnt += __shfl_down_sync(0xffffffffu, cnt, o);
        sx  += __shfl_down_sync(0xffffffffu, sx,  o);
        sy  += __shfl_down_sync(0xffffffffu, sy,  o);
        sz  += __shfl_down_sync(0xffffffffu, sz,  o);
    }
    __shared__ int   scnt[8];
    __shared__ float ss[8][3];
    if (lane == 0) { scnt[warp] = cnt; ss[warp][0] = sx; ss[warp][1] = sy; ss[warp][2] = sz; }
    __syncthreads();
    if (warp == 0) {
        cnt = (lane < 8) ? scnt[lane]  : 0;
        sx  = (lane < 8) ? ss[lane][0] : 0.f;
        sy  = (lane < 8) ? ss[lane][1] : 0.f;
        sz  = (lane < 8) ? ss[lane][2] : 0.f;
        #pragma unroll
        for (int o = 4; o; o >>= 1) {
            cnt += __shfl_down_sync(0xffffffffu, cnt, o);
            sx  += __shfl_down_sync(0xffffffffu, sx,  o);
            sy  += __shfl_down_sync(0xffffffffu, sy,  o);
            sz  += __shfl_down_sync(0xffffffffu, sz,  o);
        }
        if (lane == 0) {
            const int idx = b * NBLK + chunk;
            g_blockcnt[idx] = cnt;
            g_blocksum[idx * 3 + 0] = sx;
            g_blocksum[idx * 3 + 1] = sy;
            g_blocksum[idx * 3 + 2] = sz;
        }
    }
}

// ---------------- Kernel 2: per-batch reduce, mean, chunk offsets ----------------
__global__ void k_batch_reduce(float* __restrict__ out_mean, int has_mean) {
    const int b = blockIdx.x, lane = threadIdx.x;   // 32 threads
    const int idx = b * NBLK + lane;
    const int c = g_blockcnt[idx];
    float sx = g_blocksum[idx * 3 + 0];
    float sy = g_blocksum[idx * 3 + 1];
    float sz = g_blocksum[idx * 3 + 2];

    // inclusive scan of counts
    int inc = c;
    #pragma unroll
    for (int o = 1; o < 32; o <<= 1) {
        int v = __shfl_up_sync(0xffffffffu, inc, o);
        if (lane >= o) inc += v;
    }
    g_blockoff[idx] = inc - c;                 // exclusive prefix
    const int tot = __shfl_sync(0xffffffffu, inc, 31);

    #pragma unroll
    for (int o = 16; o; o >>= 1) {
        sx += __shfl_down_sync(0xffffffffu, sx, o);
        sy += __shfl_down_sync(0xffffffffu, sy, o);
        sz += __shfl_down_sync(0xffffffffu, sz, o);
    }
    if (lane == 0) {
        g_cnt[b] = tot;
        const float d = fmaxf((float)tot, 1.0f);
        const float mx = sx / d, my = sy / d, mz = sz / d;
        g_mean[b * 3 + 0] = mx; g_mean[b * 3 + 1] = my; g_mean[b * 3 + 2] = mz;
        if (has_mean) {
            out_mean[b * 3 + 0] = mx;
            out_mean[b * 3 + 1] = my;
            out_mean[b * 3 + 2] = mz;
        }
    }
}

// ---------------- Kernel 3: stable compaction of masked indices ----------------
__global__ void k_compact() {
    const int chunk = blockIdx.x, b = blockIdx.y;
    const int t = threadIdx.x;                // 128 threads, 1 mask word (32 pts) each
    const int lane = t & 31, warp = t >> 5;

    const int wordInBatch = chunk * (CHUNK / 32) + t;           // 0..4095
    unsigned w = g_maskbits[(size_t)b * (NPTS / 32) + wordInBatch];
    const int c = __popc(w);

    int inc = c;
    #pragma unroll
    for (int o = 1; o < 32; o <<= 1) {
        int v = __shfl_up_sync(0xffffffffu, inc, o);
        if (lane >= o) inc += v;
    }
    __shared__ int wsum[4];
    if (lane == 31) wsum[warp] = inc;
    __syncthreads();
    int woff = 0;
    if (warp > 0) woff += wsum[0];
    if (warp > 1) woff += wsum[1];
    if (warp > 2) woff += wsum[2];

    int pos = g_blockoff[b * NBLK + chunk] + woff + (inc - c);
    const int nbase = wordInBatch * 32;
    int* __restrict__ dst = g_masked_idx + (size_t)b * NPTS;
    while (w) {                                   // LSB-first = ascending index = stable
        const int bit = __ffs(w) - 1;
        dst[pos++] = nbase + bit;
        w &= (w - 1);
    }
}

// ---------------- Kernel 4: randint selection + gather + center ----------------
__global__ void k_select(const float* __restrict__ pc, float* __restrict__ out,
                         uint32_t k1a, uint32_t k1b, uint32_t k2a, uint32_t k2b) {
    const int tid = blockIdx.x * blockDim.x + threadIdx.x;   // BATCH*MPTS
    if (tid >= BATCH * MPTS) return;
    const int b = tid >> 11;                // MPTS = 2048
    const int j = tid & (MPTS - 1);
    const int cnt = g_cnt[b];
    float* __restrict__ o = out + (size_t)tid * 3;

    if (cnt == 0) {                         // empty-mask override: batch id
        const float v = (float)b;
        o[0] = v; o[1] = v; o[2] = v;
        return;
    }

    // Partitionable threefry random_bits(32): counter = (hi=0, lo=flat index),
    // output word = x0 ^ x1.
    uint32_t h0, h1, l0, l1;
    threefry2x32(k1a, k1b, 0u, (uint32_t)tid, h0, h1);
    threefry2x32(k2a, k2b, 0u, (uint32_t)tid, l0, l1);
    const uint32_t higher = h0 ^ h1;
    const uint32_t lower  = l0 ^ l1;

    const uint32_t span = (uint32_t)cnt;    // cnt >= 1 here
    uint32_t mult = 65536u % span;
    mult = (mult * mult) % span;            // uint32 wraparound — matches lax semantics
    const uint32_t ro = ((higher % span) * mult + (lower % span)) % span;
    const int rnd = (int)ro;

    const int sel = (j < cnt && cnt <= MPTS) ? j : rnd;
    const int idx = g_masked_idx[(size_t)b * NPTS + sel];

    const float4 p = __ldg((const float4*)pc + (size_t)b * NPTS + idx);
    o[0] = p.x - g_mean[b * 3 + 0];
    o[1] = p.y - g_mean[b * 3 + 1];
    o[2] = p.z - g_mean[b * 3 + 2];
}

// ---------------- launch ----------------
extern "C" void kernel_launch(void* const* d_in, const int* in_sizes, int n_in,
                              void* d_out, int out_size) {
    const float* pc     = (const float*)d_in[0];
    const float* logits = (const float*)d_in[1];
    // defensive: identify inputs by size (pc = B*N*4, logits = B*2*N)
    if (n_in >= 2 && in_sizes[0] == BATCH * 2 * NPTS && in_sizes[1] == BATCH * NPTS * 4) {
        pc     = (const float*)d_in[1];
        logits = (const float*)d_in[0];
    }
    float* out = (float*)d_out;

    // split(key(42)) — partitionable/foldlike: counters (0,0) and (0,1)
    uint32_t k1a, k1b, k2a, k2b;
    threefry2x32(0u, 42u, 0u, 0u, k1a, k1b);   // subkey for higher_bits
    threefry2x32(0u, 42u, 0u, 1u, k2a, k2b);   // subkey for lower_bits

    const size_t obj_elems = (size_t)BATCH * MPTS * 3;
    const int has_mean = (out_size >= (int)(obj_elems + BATCH * 3)) ? 1 : 0;

    k_mask_stats  <<<dim3(NBLK, BATCH), 256>>>(pc, logits);
    k_batch_reduce<<<BATCH, 32>>>(out + obj_elems, has_mean);
    k_compact     <<<dim3(NBLK, BATCH), 128>>>();
    k_select      <<<(BATCH * MPTS + 255) / 256, 256>>>(pc, out, k1a, k1b, k2a, k2b);
}

// round 2
// speedup vs baseline: 1.2501x; 1.2501x over previous
#include <cuda_runtime.h>
#include <stdint.h>

#define BATCH 64
#define NPTS  131072
#define MPTS  2048
#define CHUNK 8192
#define NBLK  (NPTS / CHUNK)      // 16 chunks per batch
#define NWORDS (NPTS / 32)        // 4096 mask words per batch

// ---- scratch (device globals; no runtime allocation) ----
__device__ __align__(16) unsigned g_maskbits[BATCH * NWORDS];   // 1 bit per point
__device__ int      g_wordpref[BATCH * NWORDS];                 // exclusive popc prefix per word
__device__ float    g_blocksum[BATCH * NBLK * 3];
__device__ int      g_cnt[BATCH];
__device__ float    g_mean[BATCH * 3];

// ---------------- Threefry-2x32 (matches JAX exactly) ----------------
__host__ __device__ inline void threefry2x32(uint32_t k0, uint32_t k1,
                                             uint32_t c0, uint32_t c1,
                                             uint32_t& o0, uint32_t& o1) {
    uint32_t ks2 = k0 ^ k1 ^ 0x1BD11BDAu;
    uint32_t x0 = c0 + k0, x1 = c1 + k1;
#define TF_ROUND(r) { x0 += x1; x1 = (x1 << (r)) | (x1 >> (32 - (r))); x1 ^= x0; }
    TF_ROUND(13) TF_ROUND(15) TF_ROUND(26) TF_ROUND(6)
    x0 += k1;  x1 += ks2 + 1u;
    TF_ROUND(17) TF_ROUND(29) TF_ROUND(16) TF_ROUND(24)
    x0 += ks2; x1 += k0 + 2u;
    TF_ROUND(13) TF_ROUND(15) TF_ROUND(26) TF_ROUND(6)
    x0 += k0;  x1 += k1 + 3u;
    TF_ROUND(17) TF_ROUND(29) TF_ROUND(16) TF_ROUND(24)
    x0 += k1;  x1 += ks2 + 4u;
    TF_ROUND(13) TF_ROUND(15) TF_ROUND(26) TF_ROUND(6)
    x0 += ks2; x1 += k0 + 5u;
#undef TF_ROUND
    o0 = x0; o1 = x1;
}

// One point: setp once, two packed f32x2 predicated adds (xy and zw; w-sum is
// discarded garbage), one predicated OR with an immediate bit weight.
#define PT(l0v, l1v, q, BIT)                                              \
    asm("{\n\t.reg .pred p;\n\t"                                          \
        "setp.lt.f32 p, %3, %4;\n\t"                                      \
        "@p add.rn.f32x2 %0, %0, %5;\n\t"                                 \
        "@p add.rn.f32x2 %1, %1, %6;\n\t"                                 \
        "@p or.b32 %2, %2, %7;\n\t}"                                      \
        : "+l"(sxy), "+l"(szw), "+r"(bits)                                \
        : "f"(l0v), "f"(l1v), "l"((q).x), "l"((q).y), "n"(BIT));

// 4 points: one float4 from each logit row, 4 longlong2 (=float4) from pc.
#define STEP(I) {                                                         \
    const float4 a = __ldg(&L0[f4base + (I)]);                            \
    const float4 c = __ldg(&L1[f4base + (I)]);                            \
    const longlong2 q0 = __ldg(&P2[p0 + 4*(I) + 0]);                      \
    const longlong2 q1 = __ldg(&P2[p0 + 4*(I) + 1]);                      \
    const longlong2 q2 = __ldg(&P2[p0 + 4*(I) + 2]);                      \
    const longlong2 q3 = __ldg(&P2[p0 + 4*(I) + 3]);                      \
    PT(a.x, c.x, q0, 1u << (4*(I)+0))                                     \
    PT(a.y, c.y, q1, 1u << (4*(I)+1))                                     \
    PT(a.z, c.z, q2, 1u << (4*(I)+2))                                     \
    PT(a.w, c.w, q3, 1u << (4*(I)+3)) }

// ---------------- Kernel 1: mask bits + per-chunk masked-xyz sums ----------------
__global__ void __launch_bounds__(256, 2)
k_mask_stats(const float* __restrict__ pc, const float* __restrict__ logits) {
    const int chunk = blockIdx.x;            // 0..NBLK-1
    const int b     = blockIdx.y;            // 0..BATCH-1
    const int t     = threadIdx.x;           // 256 threads, 32 consecutive pts each
    const int lane  = t & 31, warp = t >> 5;

    const float4*    L0 = (const float4*)(logits + (size_t)b * 2 * NPTS);
    const float4*    L1 = (const float4*)(logits + (size_t)b * 2 * NPTS + NPTS);
    const longlong2* P2 = (const longlong2*)pc + (size_t)b * NPTS;

    const int p0     = chunk * CHUNK + t * 32;   // first point of this thread
    const int f4base = p0 >> 2;

    unsigned long long sxy = 0ull, szw = 0ull;
    unsigned bits = 0u;

    STEP(0) STEP(1) STEP(2) STEP(3) STEP(4) STEP(5) STEP(6) STEP(7)

    // one mask word per thread; warp writes 128B coalesced
    g_maskbits[(size_t)b * NWORDS + (size_t)(chunk * 256 + t)] = bits;

    // unpack packed sums
    float sx, sy, sz, sw_;
    asm("mov.b64 {%0,%1}, %2;" : "=f"(sx), "=f"(sy) : "l"(sxy));
    asm("mov.b64 {%0,%1}, %2;" : "=f"(sz), "=f"(sw_) : "l"(szw));

    #pragma unroll
    for (int o = 16; o; o >>= 1) {
        sx += __shfl_down_sync(0xffffffffu, sx, o);
        sy += __shfl_down_sync(0xffffffffu, sy, o);
        sz += __shfl_down_sync(0xffffffffu, sz, o);
    }
    __shared__ float ss[8][3];
    if (lane == 0) { ss[warp][0] = sx; ss[warp][1] = sy; ss[warp][2] = sz; }
    __syncthreads();
    if (warp == 0 && lane < 8) {
        sx = ss[lane][0]; sy = ss[lane][1]; sz = ss[lane][2];
        #pragma unroll
        for (int o = 4; o; o >>= 1) {
            sx += __shfl_down_sync(0x000000ffu, sx, o);
            sy += __shfl_down_sync(0x000000ffu, sy, o);
            sz += __shfl_down_sync(0x000000ffu, sz, o);
        }
        if (lane == 0) {
            const int idx = b * NBLK + chunk;
            g_blocksum[idx * 3 + 0] = sx;
            g_blocksum[idx * 3 + 1] = sy;
            g_blocksum[idx * 3 + 2] = sz;
        }
    }
}

// ---------------- Kernel 2: per-batch word-popcount prefix + cnt + mean ----------------
__global__ void k_prefix(float* __restrict__ out_mean, int has_mean) {
    const int b = blockIdx.x;                 // one block per batch
    const int t = threadIdx.x;                // 512 threads, 8 words each
    const int lane = t & 31, warp = t >> 5;   // 16 warps

    const uint4* mb4 = (const uint4*)(g_maskbits + (size_t)b * NWORDS);
    uint4 a0 = __ldg(&mb4[t * 2 + 0]);
    uint4 a1 = __ldg(&mb4[t * 2 + 1]);

    int c[8];
    c[0] = __popc(a0.x); c[1] = __popc(a0.y); c[2] = __popc(a0.z); c[3] = __popc(a0.w);
    c[4] = __popc(a1.x); c[5] = __popc(a1.y); c[6] = __popc(a1.z); c[7] = __popc(a1.w);

    int lp[8]; int s = 0;
    #pragma unroll
    for (int i = 0; i < 8; ++i) { lp[i] = s; s += c[i]; }

    // warp inclusive scan of s
    int inc = s;
    #pragma unroll
    for (int o = 1; o < 32; o <<= 1) {
        int v = __shfl_up_sync(0xffffffffu, inc, o);
        if (lane >= o) inc += v;
    }
    __shared__ int swarp[16];
    __shared__ int swpref[16];
    __shared__ int stot;
    if (lane == 31) swarp[warp] = inc;
    __syncthreads();
    if (warp == 0 && lane < 16) {
        int v = swarp[lane], winc = v;
        #pragma unroll
        for (int o = 1; o < 16; o <<= 1) {
            int u = __shfl_up_sync(0x0000ffffu, winc, o);
            if (lane >= o) winc += u;
        }
        swpref[lane] = winc - v;              // exclusive
        if (lane == 15) stot = winc;
    }
    __syncthreads();

    const int off = swpref[warp] + (inc - s); // exclusive prefix of this thread
    int* __restrict__ pref = g_wordpref + (size_t)b * NWORDS + t * 8;
    #pragma unroll
    for (int i = 0; i < 8; ++i) pref[i] = off + lp[i];

    const int tot = stot;
    if (t == 0) g_cnt[b] = tot;

    // mean from the 16 chunk partial sums
    if (t < 32) {
        float sx = 0.f, sy = 0.f, sz = 0.f;
        if (lane < NBLK) {
            const int idx = b * NBLK + lane;
            sx = g_blocksum[idx * 3 + 0];
            sy = g_blocksum[idx * 3 + 1];
            sz = g_blocksum[idx * 3 + 2];
        }
        #pragma unroll
        for (int o = 8; o; o >>= 1) {
            sx += __shfl_down_sync(0xffffffffu, sx, o);
            sy += __shfl_down_sync(0xffffffffu, sy, o);
            sz += __shfl_down_sync(0xffffffffu, sz, o);
        }
        if (lane == 0) {
            const float d = fmaxf((float)tot, 1.0f);
            const float mx = sx / d, my = sy / d, mz = sz / d;
            g_mean[b * 3 + 0] = mx; g_mean[b * 3 + 1] = my; g_mean[b * 3 + 2] = mz;
            if (has_mean) {
                out_mean[b * 3 + 0] = mx;
                out_mean[b * 3 + 1] = my;
                out_mean[b * 3 + 2] = mz;
            }
        }
    }
}

// ---------------- Kernel 3: randint + rank/select via prefix + gather + center ----------------
__global__ void k_select(const float* __restrict__ pc, float* __restrict__ out,
                         uint32_t k1a, uint32_t k1b, uint32_t k2a, uint32_t k2b) {
    const int tid = blockIdx.x * blockDim.x + threadIdx.x;   // BATCH*MPTS
    if (tid >= BATCH * MPTS) return;
    const int b = tid >> 11;                 // MPTS = 2048
    const int j = tid & (MPTS - 1);
    const int cnt = __ldg(&g_cnt[b]);
    float* __restrict__ o = out + (size_t)tid * 3;

    if (cnt == 0) {                          // empty-mask override: batch id
        const float v = (float)b;
        o[0] = v; o[1] = v; o[2] = v;
        return;
    }

    // Partitionable threefry random_bits(32): counter = (0, flat index), word = x0^x1
    uint32_t h0, h1, l0, l1;
    threefry2x32(k1a, k1b, 0u, (uint32_t)tid, h0, h1);
    threefry2x32(k2a, k2b, 0u, (uint32_t)tid, l0, l1);
    const uint32_t higher = h0 ^ h1;
    const uint32_t lower  = l0 ^ l1;

    const uint32_t span = (uint32_t)cnt;
    uint32_t mult = 65536u % span;
    mult = (mult * mult) % span;             // uint32 wraparound — matches lax semantics
    const int rnd = (int)(((higher % span) * mult + (lower % span)) % span);

    const int sel = (j < cnt && cnt <= MPTS) ? j : rnd;

    // binary search: largest word w with pref[w] <= sel (pref exclusive, pref[0]=0)
    const int* __restrict__ pref = g_wordpref + (size_t)b * NWORDS;
    int lo = 0, hi = NWORDS, plo = 0;
    #pragma unroll
    for (int s = 0; s < 12; ++s) {           // 2^12 = 4096
        const int mid = (lo + hi) >> 1;
        const int v = __ldg(&pref[mid]);
        const bool le = (v <= sel);
        lo  = le ? mid : lo;
        plo = le ? v   : plo;
        hi  = le ? hi  : mid;
    }
    unsigned w = __ldg(&g_maskbits[(size_t)b * NWORDS + lo]);
    int r = sel - plo;                       // r-th set bit of w (0-based)

    // branch-free popcount ladder
    int p = 0;
    {
        int cc = __popc(w & 0xFFFFu); if (r >= cc) { r -= cc; p += 16; w >>= 16; }
        cc = __popc(w & 0xFFu);       if (r >= cc) { r -= cc; p += 8;  w >>= 8;  }
        cc = __popc(w & 0xFu);        if (r >= cc) { r -= cc; p += 4;  w >>= 4;  }
        cc = __popc(w & 0x3u);        if (r >= cc) { r -= cc; p += 2;  w >>= 2;  }
        cc = (int)(w & 1u);           if (r >= cc) {          p += 1;            }
    }
    const int idx = lo * 32 + p;

    const float4 pt = __ldg((const float4*)pc + (size_t)b * NPTS + idx);
    o[0] = pt.x - __ldg(&g_mean[b * 3 + 0]);
    o[1] = pt.y - __ldg(&g_mean[b * 3 + 1]);
    o[2] = pt.z - __ldg(&g_mean[b * 3 + 2]);
}

// ---------------- launch ----------------
extern "C" void kernel_launch(void* const* d_in, const int* in_sizes, int n_in,
                              void* d_out, int out_size) {
    const float* pc     = (const float*)d_in[0];
    const float* logits = (const float*)d_in[1];
    if (n_in >= 2 && in_sizes[0] == BATCH * 2 * NPTS && in_sizes[1] == BATCH * NPTS * 4) {
        pc     = (const float*)d_in[1];
        logits = (const float*)d_in[0];
    }
    float* out = (float*)d_out;

    // split(key(42)) — partitionable/foldlike: counters (0,0) and (0,1)
    uint32_t k1a, k1b, k2a, k2b;
    threefry2x32(0u, 42u, 0u, 0u, k1a, k1b);
    threefry2x32(0u, 42u, 0u, 1u, k2a, k2b);

    const size_t obj_elems = (size_t)BATCH * MPTS * 3;
    const int has_mean = (out_size >= (int)(obj_elems + BATCH * 3)) ? 1 : 0;

    k_mask_stats<<<dim3(NBLK, BATCH), 256>>>(pc, logits);
    k_prefix    <<<BATCH, 512>>>(out + obj_elems, has_mean);
    k_select    <<<(BATCH * MPTS + 255) / 256, 256>>>(pc, out, k1a, k1b, k2a, k2b);
}

// round 3
// speedup vs baseline: 1.7882x; 1.4304x over previous
#include <cuda_runtime.h>
#include <stdint.h>

#define BATCH 64
#define NPTS  131072
#define MPTS  2048
#define TILE  2048                 // points per block in k_mask_stats
#define NTILE (NPTS / TILE)        // 64 tiles per batch
#define NWORDS (NPTS / 32)         // 4096 mask words per batch

// ---- scratch (device globals; no runtime allocation) ----
__device__ __align__(16) unsigned g_maskbits[BATCH * NWORDS];   // 1 bit per point
__device__ int      g_wordpref[BATCH * NWORDS];                 // exclusive popc prefix per word
__device__ float    g_blocksum[BATCH * NTILE * 3];              // per-tile masked xyz sums
__device__ int      g_cnt[BATCH];
__device__ float    g_mean[BATCH * 3];

// ---------------- Threefry-2x32 (matches JAX exactly) ----------------
__host__ __device__ inline void threefry2x32(uint32_t k0, uint32_t k1,
                                             uint32_t c0, uint32_t c1,
                                             uint32_t& o0, uint32_t& o1) {
    uint32_t ks2 = k0 ^ k1 ^ 0x1BD11BDAu;
    uint32_t x0 = c0 + k0, x1 = c1 + k1;
#define TF_ROUND(r) { x0 += x1; x1 = (x1 << (r)) | (x1 >> (32 - (r))); x1 ^= x0; }
    TF_ROUND(13) TF_ROUND(15) TF_ROUND(26) TF_ROUND(6)
    x0 += k1;  x1 += ks2 + 1u;
    TF_ROUND(17) TF_ROUND(29) TF_ROUND(16) TF_ROUND(24)
    x0 += ks2; x1 += k0 + 2u;
    TF_ROUND(13) TF_ROUND(15) TF_ROUND(26) TF_ROUND(6)
    x0 += k0;  x1 += k1 + 3u;
    TF_ROUND(17) TF_ROUND(29) TF_ROUND(16) TF_ROUND(24)
    x0 += k1;  x1 += ks2 + 4u;
    TF_ROUND(13) TF_ROUND(15) TF_ROUND(26) TF_ROUND(6)
    x0 += ks2; x1 += k0 + 5u;
#undef TF_ROUND
    o0 = x0; o1 = x1;
}

// ---------------- Kernel 1: mask bits + per-tile masked-xyz sums ----------------
// Lane-contiguous layout: point n = warpbase + 32*k + lane. Every warp-level
// load is a single contiguous 128B (scalar) or 512B (float4) transaction, and
// __ballot_sync directly produces the 32-point mask word in index order.
__global__ void __launch_bounds__(256)
k_mask_stats(const float* __restrict__ pc, const float* __restrict__ logits) {
    const int tile = blockIdx.x;             // 0..NTILE-1
    const int b    = blockIdx.y;             // 0..BATCH-1
    const int lane = threadIdx.x & 31, warp = threadIdx.x >> 5;

    const float*  l0 = logits + (size_t)b * 2 * NPTS;
    const float*  l1 = l0 + NPTS;
    const float4* p4 = (const float4*)pc + (size_t)b * NPTS;

    const int wbase = tile * TILE + warp * 256;   // this warp's 256 points
    float sx = 0.f, sy = 0.f, sz = 0.f;

    #pragma unroll
    for (int k = 0; k < 8; ++k) {
        const int n = wbase + k * 32 + lane;
        const bool m = __ldg(&l0[n]) < __ldg(&l1[n]);
        const unsigned bal = __ballot_sync(0xffffffffu, m);
        const float4 p = __ldg(&p4[n]);
        if (lane == 0)
            g_maskbits[(size_t)b * NWORDS + (unsigned)(wbase + k * 32) / 32] = bal;
        if (m) { sx += p.x; sy += p.y; sz += p.z; }
    }

    #pragma unroll
    for (int o = 16; o; o >>= 1) {
        sx += __shfl_down_sync(0xffffffffu, sx, o);
        sy += __shfl_down_sync(0xffffffffu, sy, o);
        sz += __shfl_down_sync(0xffffffffu, sz, o);
    }
    __shared__ float ss[8][3];
    if (lane == 0) { ss[warp][0] = sx; ss[warp][1] = sy; ss[warp][2] = sz; }
    __syncthreads();
    if (warp == 0 && lane < 8) {
        sx = ss[lane][0]; sy = ss[lane][1]; sz = ss[lane][2];
        #pragma unroll
        for (int o = 4; o; o >>= 1) {
            sx += __shfl_down_sync(0x000000ffu, sx, o);
            sy += __shfl_down_sync(0x000000ffu, sy, o);
            sz += __shfl_down_sync(0x000000ffu, sz, o);
        }
        if (lane == 0) {
            const int idx = b * NTILE + tile;
            g_blocksum[idx * 3 + 0] = sx;
            g_blocksum[idx * 3 + 1] = sy;
            g_blocksum[idx * 3 + 2] = sz;
        }
    }
}

// ---------------- Kernel 2: per-batch word-popcount prefix + cnt + mean ----------------
__global__ void k_prefix(float* __restrict__ out_mean, int has_mean) {
    const int b = blockIdx.x;                 // one block per batch
    const int t = threadIdx.x;                // 512 threads, 8 words each
    const int lane = t & 31, warp = t >> 5;   // 16 warps

    const uint4* mb4 = (const uint4*)(g_maskbits + (size_t)b * NWORDS);
    uint4 a0 = __ldg(&mb4[t * 2 + 0]);
    uint4 a1 = __ldg(&mb4[t * 2 + 1]);

    int c[8];
    c[0] = __popc(a0.x); c[1] = __popc(a0.y); c[2] = __popc(a0.z); c[3] = __popc(a0.w);
    c[4] = __popc(a1.x); c[5] = __popc(a1.y); c[6] = __popc(a1.z); c[7] = __popc(a1.w);

    int lp[8]; int s = 0;
    #pragma unroll
    for (int i = 0; i < 8; ++i) { lp[i] = s; s += c[i]; }

    int inc = s;
    #pragma unroll
    for (int o = 1; o < 32; o <<= 1) {
        int v = __shfl_up_sync(0xffffffffu, inc, o);
        if (lane >= o) inc += v;
    }
    __shared__ int swarp[16];
    __shared__ int swpref[16];
    __shared__ int stot;
    if (lane == 31) swarp[warp] = inc;
    __syncthreads();
    if (warp == 0 && lane < 16) {
        int v = swarp[lane], winc = v;
        #pragma unroll
        for (int o = 1; o < 16; o <<= 1) {
            int u = __shfl_up_sync(0x0000ffffu, winc, o);
            if (lane >= o) winc += u;
        }
        swpref[lane] = winc - v;              // exclusive
        if (lane == 15) stot = winc;
    }
    __syncthreads();

    const int off = swpref[warp] + (inc - s);
    int* __restrict__ pref = g_wordpref + (size_t)b * NWORDS + t * 8;
    #pragma unroll
    for (int i = 0; i < 8; ++i) pref[i] = off + lp[i];

    const int tot = stot;
    if (t == 0) g_cnt[b] = tot;

    // mean from the 64 per-tile partial sums
    if (t < 32) {
        const int i0 = (b * NTILE + lane) * 3;
        const int i1 = (b * NTILE + lane + 32) * 3;
        float sx = g_blocksum[i0 + 0] + g_blocksum[i1 + 0];
        float sy = g_blocksum[i0 + 1] + g_blocksum[i1 + 1];
        float sz = g_blocksum[i0 + 2] + g_blocksum[i1 + 2];
        #pragma unroll
        for (int o = 16; o; o >>= 1) {
            sx += __shfl_down_sync(0xffffffffu, sx, o);
            sy += __shfl_down_sync(0xffffffffu, sy, o);
            sz += __shfl_down_sync(0xffffffffu, sz, o);
        }
        if (lane == 0) {
            const float d = fmaxf((float)tot, 1.0f);
            const float mx = sx / d, my = sy / d, mz = sz / d;
            g_mean[b * 3 + 0] = mx; g_mean[b * 3 + 1] = my; g_mean[b * 3 + 2] = mz;
            if (has_mean) {
                out_mean[b * 3 + 0] = mx;
                out_mean[b * 3 + 1] = my;
                out_mean[b * 3 + 2] = mz;
            }
        }
    }
}

// ---------------- Kernel 3: randint + rank/select via prefix + gather + center ----------------
__global__ void k_select(const float* __restrict__ pc, float* __restrict__ out,
                         uint32_t k1a, uint32_t k1b, uint32_t k2a, uint32_t k2b) {
    const int tid = blockIdx.x * blockDim.x + threadIdx.x;   // BATCH*MPTS
    if (tid >= BATCH * MPTS) return;
    const int b = tid >> 11;                 // MPTS = 2048
    const int j = tid & (MPTS - 1);
    const int cnt = __ldg(&g_cnt[b]);
    float* __restrict__ o = out + (size_t)tid * 3;

    if (cnt == 0) {                          // empty-mask override: batch id
        const float v = (float)b;
        o[0] = v; o[1] = v; o[2] = v;
        return;
    }

    // Partitionable threefry random_bits(32): counter = (0, flat index), word = x0^x1
    uint32_t h0, h1, l0, l1;
    threefry2x32(k1a, k1b, 0u, (uint32_t)tid, h0, h1);
    threefry2x32(k2a, k2b, 0u, (uint32_t)tid, l0, l1);
    const uint32_t higher = h0 ^ h1;
    const uint32_t lower  = l0 ^ l1;

    const uint32_t span = (uint32_t)cnt;
    uint32_t mult = 65536u % span;
    mult = (mult * mult) % span;             // uint32 wraparound — matches lax semantics
    const int rnd = (int)(((higher % span) * mult + (lower % span)) % span);

    const int sel = (j < cnt && cnt <= MPTS) ? j : rnd;

    // binary search: largest word w with pref[w] <= sel (pref exclusive, pref[0]=0)
    const int* __restrict__ pref = g_wordpref + (size_t)b * NWORDS;
    int lo = 0, hi = NWORDS, plo = 0;
    #pragma unroll
    for (int s = 0; s < 12; ++s) {           // 2^12 = 4096
        const int mid = (lo + hi) >> 1;
        const int v = __ldg(&pref[mid]);
        const bool le = (v <= sel);
        lo  = le ? mid : lo;
        plo = le ? v   : plo;
        hi  = le ? hi  : mid;
    }
    unsigned w = __ldg(&g_maskbits[(size_t)b * NWORDS + lo]);
    int r = sel - plo;                       // r-th set bit of w (0-based)

    int p = 0;
    {
        int cc = __popc(w & 0xFFFFu); if (r >= cc) { r -= cc; p += 16; w >>= 16; }
        cc = __popc(w & 0xFFu);       if (r >= cc) { r -= cc; p += 8;  w >>= 8;  }
        cc = __popc(w & 0xFu);        if (r >= cc) { r -= cc; p += 4;  w >>= 4;  }
        cc = __popc(w & 0x3u);        if (r >= cc) { r -= cc; p += 2;  w >>= 2;  }
        cc = (int)(w & 1u);           if (r >= cc) {          p += 1;            }
    }
    const int idx = lo * 32 + p;

    const float4 pt = __ldg((const float4*)pc + (size_t)b * NPTS + idx);
    o[0] = pt.x - __ldg(&g_mean[b * 3 + 0]);
    o[1] = pt.y - __ldg(&g_mean[b * 3 + 1]);
    o[2] = pt.z - __ldg(&g_mean[b * 3 + 2]);
}

// ---------------- launch ----------------
extern "C" void kernel_launch(void* const* d_in, const int* in_sizes, int n_in,
                              void* d_out, int out_size) {
    const float* pc     = (const float*)d_in[0];
    const float* logits = (const float*)d_in[1];
    if (n_in >= 2 && in_sizes[0] == BATCH * 2 * NPTS && in_sizes[1] == BATCH * NPTS * 4) {
        pc     = (const float*)d_in[1];
        logits = (const float*)d_in[0];
    }
    float* out = (float*)d_out;

    // split(key(42)) — partitionable/foldlike: counters (0,0) and (0,1)
    uint32_t k1a, k1b, k2a, k2b;
    threefry2x32(0u, 42u, 0u, 0u, k1a, k1b);
    threefry2x32(0u, 42u, 0u, 1u, k2a, k2b);

    const size_t obj_elems = (size_t)BATCH * MPTS * 3;
    const int has_mean = (out_size >= (int)(obj_elems + BATCH * 3)) ? 1 : 0;

    k_mask_stats<<<dim3(NTILE, BATCH), 256>>>(pc, logits);
    k_prefix    <<<BATCH, 512>>>(out + obj_elems, has_mean);
    k_select    <<<(BATCH * MPTS + 255) / 256, 256>>>(pc, out, k1a, k1b, k2a, k2b);
}

// round 4
// speedup vs baseline: 1.8581x; 1.0391x over previous
#include <cuda_runtime.h>
#include <stdint.h>

#define BATCH 64
#define NPTS  131072
#define MPTS  2048
#define TILE  2048                 // points per block in k_mask_stats
#define NTILE (NPTS / TILE)        // 64 tiles per batch
#define NWORDS (NPTS / 32)         // 4096 mask words per batch

// ---- scratch (device globals; no runtime allocation) ----
__device__ __align__(16) unsigned g_maskbits[BATCH * NWORDS];   // 1 bit per point
__device__ float    g_blocksum[BATCH * NTILE * 3];              // per-tile masked xyz sums
__device__ uint32_t g_hi[BATCH * MPTS];                         // precomputed threefry draws
__device__ uint32_t g_lo[BATCH * MPTS];

// ---------------- Threefry-2x32 (matches JAX exactly) ----------------
__host__ __device__ inline void threefry2x32(uint32_t k0, uint32_t k1,
                                             uint32_t c0, uint32_t c1,
                                             uint32_t& o0, uint32_t& o1) {
    uint32_t ks2 = k0 ^ k1 ^ 0x1BD11BDAu;
    uint32_t x0 = c0 + k0, x1 = c1 + k1;
#define TF_ROUND(r) { x0 += x1; x1 = (x1 << (r)) | (x1 >> (32 - (r))); x1 ^= x0; }
    TF_ROUND(13) TF_ROUND(15) TF_ROUND(26) TF_ROUND(6)
    x0 += k1;  x1 += ks2 + 1u;
    TF_ROUND(17) TF_ROUND(29) TF_ROUND(16) TF_ROUND(24)
    x0 += ks2; x1 += k0 + 2u;
    TF_ROUND(13) TF_ROUND(15) TF_ROUND(26) TF_ROUND(6)
    x0 += k0;  x1 += k1 + 3u;
    TF_ROUND(17) TF_ROUND(29) TF_ROUND(16) TF_ROUND(24)
    x0 += k1;  x1 += ks2 + 4u;
    TF_ROUND(13) TF_ROUND(15) TF_ROUND(26) TF_ROUND(6)
    x0 += ks2; x1 += k0 + 5u;
#undef TF_ROUND
    o0 = x0; o1 = x1;
}

// ---------------- Kernel 1: mask bits + per-tile masked-xyz sums + threefry precompute ----------
__global__ void __launch_bounds__(256)
k_mask_stats(const float* __restrict__ pc, const float* __restrict__ logits,
             uint32_t k1a, uint32_t k1b, uint32_t k2a, uint32_t k2b) {
    const int tile = blockIdx.x;             // 0..NTILE-1
    const int b    = blockIdx.y;             // 0..BATCH-1
    const int lane = threadIdx.x & 31, warp = threadIdx.x >> 5;

    const float*  l0 = logits + (size_t)b * 2 * NPTS;
    const float*  l1 = l0 + NPTS;
    const float4* p4 = (const float4*)pc + (size_t)b * NPTS;

    const int wbase = tile * TILE + warp * 256;   // this warp's 256 points
    float sx = 0.f, sy = 0.f, sz = 0.f;

    #pragma unroll
    for (int k = 0; k < 8; ++k) {
        const int n = wbase + k * 32 + lane;
        const bool m = __ldg(&l0[n]) < __ldg(&l1[n]);
        const unsigned bal = __ballot_sync(0xffffffffu, m);
        const float4 p = __ldg(&p4[n]);
        if (lane == 0)
            g_maskbits[(size_t)b * NWORDS + (unsigned)(wbase + k * 32) / 32] = bal;
        if (m) { sx += p.x; sy += p.y; sz += p.z; }
    }

    // Free ALU under the memory shadow: warp 0 computes this block's 32
    // threefry draws for the selection kernel (slot = b*MPTS + tile*32 + lane).
    if (warp == 0) {
        const uint32_t slot = (uint32_t)(b * MPTS + tile * 32 + lane);
        uint32_t h0, h1, q0, q1;
        threefry2x32(k1a, k1b, 0u, slot, h0, h1);
        threefry2x32(k2a, k2b, 0u, slot, q0, q1);
        g_hi[slot] = h0 ^ h1;
        g_lo[slot] = q0 ^ q1;
    }

    #pragma unroll
    for (int o = 16; o; o >>= 1) {
        sx += __shfl_down_sync(0xffffffffu, sx, o);
        sy += __shfl_down_sync(0xffffffffu, sy, o);
        sz += __shfl_down_sync(0xffffffffu, sz, o);
    }
    __shared__ float ss[8][3];
    if (lane == 0) { ss[warp][0] = sx; ss[warp][1] = sy; ss[warp][2] = sz; }
    __syncthreads();
    if (warp == 0 && lane < 8) {
        sx = ss[lane][0]; sy = ss[lane][1]; sz = ss[lane][2];
        #pragma unroll
        for (int o = 4; o; o >>= 1) {
            sx += __shfl_down_sync(0x000000ffu, sx, o);
            sy += __shfl_down_sync(0x000000ffu, sy, o);
            sz += __shfl_down_sync(0x000000ffu, sz, o);
        }
        if (lane == 0) {
            const int idx = b * NTILE + tile;
            g_blocksum[idx * 3 + 0] = sx;
            g_blocksum[idx * 3 + 1] = sy;
            g_blocksum[idx * 3 + 2] = sz;
        }
    }
}

// ---------------- Kernel 2: fused prefix + mean + selection (one block per batch) ----------------
__global__ void __launch_bounds__(512)
k_prefix_select(const float* __restrict__ pc, float* __restrict__ out, int has_mean) {
    const int b = blockIdx.x;                 // one block per batch
    const int t = threadIdx.x;                // 512 threads
    const int lane = t & 31, warp = t >> 5;   // 16 warps

    __shared__ int      s_pref[NWORDS];       // 16 KB: exclusive popc prefix
    __shared__ unsigned s_word[NWORDS];       // 16 KB: mask words
    __shared__ int      swarp[16], swpref[16], stot;
    __shared__ float    smean[3];

    // ---- Phase A: load words, popcount prefix ----
    const uint4* mb4 = (const uint4*)(g_maskbits + (size_t)b * NWORDS);
    uint4 a0 = __ldg(&mb4[t * 2 + 0]);
    uint4 a1 = __ldg(&mb4[t * 2 + 1]);
    ((uint4*)s_word)[t * 2 + 0] = a0;
    ((uint4*)s_word)[t * 2 + 1] = a1;

    int c[8];
    c[0] = __popc(a0.x); c[1] = __popc(a0.y); c[2] = __popc(a0.z); c[3] = __popc(a0.w);
    c[4] = __popc(a1.x); c[5] = __popc(a1.y); c[6] = __popc(a1.z); c[7] = __popc(a1.w);

    int lp[8]; int s = 0;
    #pragma unroll
    for (int i = 0; i < 8; ++i) { lp[i] = s; s += c[i]; }

    int inc = s;
    #pragma unroll
    for (int o = 1; o < 32; o <<= 1) {
        int v = __shfl_up_sync(0xffffffffu, inc, o);
        if (lane >= o) inc += v;
    }
    if (lane == 31) swarp[warp] = inc;
    __syncthreads();
    if (warp == 0 && lane < 16) {
        int v = swarp[lane], winc = v;
        #pragma unroll
        for (int o = 1; o < 16; o <<= 1) {
            int u = __shfl_up_sync(0x0000ffffu, winc, o);
            if (lane >= o) winc += u;
        }
        swpref[lane] = winc - v;
        if (lane == 15) stot = winc;
    }
    __syncthreads();

    const int off = swpref[warp] + (inc - s);
    #pragma unroll
    for (int i = 0; i < 8; ++i) s_pref[t * 8 + i] = off + lp[i];

    // mean from the 64 per-tile partial sums (warp 1 while others proceed to barrier)
    if (warp == 1) {
        const int i0 = (b * NTILE + lane) * 3;
        const int i1 = (b * NTILE + lane + 32) * 3;
        float sx = g_blocksum[i0 + 0] + g_blocksum[i1 + 0];
        float sy = g_blocksum[i0 + 1] + g_blocksum[i1 + 1];
        float sz = g_blocksum[i0 + 2] + g_blocksum[i1 + 2];
        #pragma unroll
        for (int o = 16; o; o >>= 1) {
            sx += __shfl_down_sync(0xffffffffu, sx, o);
            sy += __shfl_down_sync(0xffffffffu, sy, o);
            sz += __shfl_down_sync(0xffffffffu, sz, o);
        }
        if (lane == 0) {
            const float d = fmaxf((float)stot, 1.0f);
            const float mx = sx / d, my = sy / d, mz = sz / d;
            smean[0] = mx; smean[1] = my; smean[2] = mz;
            if (has_mean) {
                float* om = out + (size_t)BATCH * MPTS * 3;
                om[b * 3 + 0] = mx; om[b * 3 + 1] = my; om[b * 3 + 2] = mz;
            }
        }
    }
    __syncthreads();

    // ---- Phase B: 4 selections per thread ----
    const int cnt = stot;
    const float mx = smean[0], my = smean[1], mz = smean[2];

    if (cnt == 0) {
        const float v = (float)b;
        #pragma unroll
        for (int i = 0; i < 4; ++i) {
            float* o = out + ((size_t)b * MPTS + (size_t)(t + i * 512)) * 3;
            o[0] = v; o[1] = v; o[2] = v;
        }
        return;
    }

    const uint32_t span = (uint32_t)cnt;
    uint32_t mult = 65536u % span;
    mult = (mult * mult) % span;              // uint32 wraparound — matches lax semantics
    const bool small = (cnt <= MPTS);

    #pragma unroll
    for (int i = 0; i < 4; ++i) {
        const int j = t + i * 512;
        const int slot = b * MPTS + j;
        const uint32_t higher = __ldg(&g_hi[slot]);
        const uint32_t lower  = __ldg(&g_lo[slot]);
        const int rnd = (int)(((higher % span) * mult + (lower % span)) % span);
        const int sel = (small && j < cnt) ? j : rnd;

        // binary search in smem: largest word w with pref[w] <= sel
        int lo = 0, hi = NWORDS, plo = 0;
        #pragma unroll
        for (int st = 0; st < 12; ++st) {
            const int mid = (lo + hi) >> 1;
            const int v = s_pref[mid];
            const bool le = (v <= sel);
            lo  = le ? mid : lo;
            plo = le ? v   : plo;
            hi  = le ? hi  : mid;
        }
        unsigned w = s_word[lo];
        int r = sel - plo;

        int p = 0;
        {
            int cc = __popc(w & 0xFFFFu); if (r >= cc) { r -= cc; p += 16; w >>= 16; }
            cc = __popc(w & 0xFFu);       if (r >= cc) { r -= cc; p += 8;  w >>= 8;  }
            cc = __popc(w & 0xFu);        if (r >= cc) { r -= cc; p += 4;  w >>= 4;  }
            cc = __popc(w & 0x3u);        if (r >= cc) { r -= cc; p += 2;  w >>= 2;  }
            cc = (int)(w & 1u);           if (r >= cc) {          p += 1;            }
        }
        const int idx = lo * 32 + p;

        const float4 pt = __ldg((const float4*)pc + (size_t)b * NPTS + idx);
        float* o = out + (size_t)slot * 3;
        o[0] = pt.x - mx;
        o[1] = pt.y - my;
        o[2] = pt.z - mz;
    }
}

// ---------------- launch ----------------
extern "C" void kernel_launch(void* const* d_in, const int* in_sizes, int n_in,
                              void* d_out, int out_size) {
    const float* pc     = (const float*)d_in[0];
    const float* logits = (const float*)d_in[1];
    if (n_in >= 2 && in_sizes[0] == BATCH * 2 * NPTS && in_sizes[1] == BATCH * NPTS * 4) {
        pc     = (const float*)d_in[1];
        logits = (const float*)d_in[0];
    }
    float* out = (float*)d_out;

    // split(key(42)) — partitionable/foldlike: counters (0,0) and (0,1)
    uint32_t k1a, k1b, k2a, k2b;
    threefry2x32(0u, 42u, 0u, 0u, k1a, k1b);
    threefry2x32(0u, 42u, 0u, 1u, k2a, k2b);

    const size_t obj_elems = (size_t)BATCH * MPTS * 3;
    const int has_mean = (out_size >= (int)(obj_elems + BATCH * 3)) ? 1 : 0;

    k_mask_stats   <<<dim3(NTILE, BATCH), 256>>>(pc, logits, k1a, k1b, k2a, k2b);
    k_prefix_select<<<BATCH, 512>>>(pc, out, has_mean);
}